// round 15
// baseline (speedup 1.0000x reference)
#include <cuda_runtime.h>
#include <cuda_bf16.h>
#include <cuda_fp16.h>
#include <cstdint>

// GNN_9869834846215: two-layer cached GCN.
//   g = dinv ⊙ (h W) (fp16)  -- cp.async-pipelined HMMA bf16x2-split GEMM
//   out[d] = dinv[d]*(Σ_{s∈N(d)} g[s] + g[d]) + b
// agg1 and gemm2 are software-pipelined in 2 row chunks across two streams.

#define NMAX 100000
#define EMAX 1700000
#define FD 128
#define SCAN_T 1024
#define SCAN_C 4096
#define SCAN_NBLK 25
#define NSM 148

#define BSTRIDE 136                        // bf16 smem row stride (272B)
#define B_SH (128 * BSTRIDE * 2)           // 34816 B per B image
#define A_STG (32 * BSTRIDE * 2)           // 8704 B per 32-row A image
#define GEMM_SMEM (2 * B_SH + 2 * 2 * A_STG)  // 104448 -> 2 blocks/SM

// Scratch (__device__ globals; d_degi zero-init, re-zeroed by scan_add)
__device__ float d_dinv[NMAX];
__device__ float d_bufA[(size_t)NMAX * FD];            // g (fp16 view)
__device__ __align__(16) unsigned short d_xhi[(size_t)NMAX * FD];
__device__ __align__(16) unsigned short d_xlo[(size_t)NMAX * FD];
__device__ __align__(16) unsigned short d_hhi[(size_t)NMAX * FD];
__device__ __align__(16) unsigned short d_hlo[(size_t)NMAX * FD];
__device__ int   d_degi[NMAX];             // starts zeroed; scan_add re-zeroes
__device__ int   d_off[NMAX + 1];
__device__ int   d_cursor[NMAX];
__device__ int   d_csr[EMAX];
__device__ int   d_blocksums[32];
__device__ __align__(16) unsigned short d_W1hi[128 * BSTRIDE];
__device__ __align__(16) unsigned short d_W1lo[128 * BSTRIDE];
__device__ __align__(16) unsigned short d_W2hi[128 * BSTRIDE];
__device__ __align__(16) unsigned short d_W2lo[128 * BSTRIDE];

// ---------------------------------------------------------------------------
__device__ __forceinline__ uint32_t smem_u32(const void* p) {
    uint32_t a;
    asm("{ .reg .u64 t; cvta.to.shared.u64 t, %1; cvt.u32.u64 %0, t; }"
        : "=r"(a) : "l"(p));
    return a;
}
__device__ __forceinline__ void ldm_x4(uint32_t* r, uint32_t addr) {
    asm volatile("ldmatrix.sync.aligned.m8n8.x4.shared.b16 {%0,%1,%2,%3}, [%4];"
                 : "=r"(r[0]), "=r"(r[1]), "=r"(r[2]), "=r"(r[3]) : "r"(addr));
}
__device__ __forceinline__ void mma_bf16(float* c, const uint32_t* a,
                                         const uint32_t* b) {
    asm volatile(
        "mma.sync.aligned.m16n8k16.row.col.f32.bf16.bf16.f32 "
        "{%0,%1,%2,%3}, {%4,%5,%6,%7}, {%8,%9}, {%0,%1,%2,%3};"
        : "+f"(c[0]), "+f"(c[1]), "+f"(c[2]), "+f"(c[3])
        : "r"(a[0]), "r"(a[1]), "r"(a[2]), "r"(a[3]), "r"(b[0]), "r"(b[1]));
}
__device__ __forceinline__ void cp16(uint32_t smem, const void* g) {
    asm volatile("cp.async.cg.shared.global [%0], [%1], 16;"
                 :: "r"(smem), "l"(g) : "memory");
}
__device__ __forceinline__ unsigned short bfbits(__nv_bfloat16 h) {
    return __bfloat16_as_ushort(h);
}
__device__ __forceinline__ int detect64_local(const void* ei, int* s64) {
    if (threadIdx.x == 0) {
        const int2* p = (const int2*)ei;
        int is64 = 1;
        for (int j = 0; j < 64; ++j)
            if (p[j].y != 0) { is64 = 0; break; }
        *s64 = is64;
    }
    __syncthreads();
    return *s64;
}

// ---------------------------------------------------------------------------
__device__ __forceinline__ void w_split_elem(const float* W,
                                             unsigned short* hi,
                                             unsigned short* lo, int idx) {
    int nn = idx & 127, kk = idx >> 7;
    float v = W[kk * FD + nn];
    __nv_bfloat16 h = __float2bfloat16_rn(v);
    __nv_bfloat16 l = __float2bfloat16_rn(v - __bfloat162float(h));
    hi[nn * BSTRIDE + kk] = bfbits(h);
    lo[nn * BSTRIDE + kk] = bfbits(l);
}

// Fused prepass: blocks [0,64) split W1; blocks [64,..) grid-stride split x.
__global__ void split_all(const float* __restrict__ x,
                          const float* __restrict__ W1,
                          unsigned short* __restrict__ hi,
                          unsigned short* __restrict__ lo, int total8) {
    if (blockIdx.x < 64) {
        int idx = blockIdx.x * 256 + threadIdx.x;
        if (idx < 16384) w_split_elem(W1, d_W1hi, d_W1lo, idx);
        return;
    }
    const int nb = gridDim.x - 64;
    for (int i = (blockIdx.x - 64) * blockDim.x + threadIdx.x; i < total8;
         i += nb * blockDim.x) {
        const float4* src = (const float4*)x + 2 * (size_t)i;
        float4 v0 = __ldg(src);
        float4 v1 = __ldg(src + 1);
        float f[8] = {v0.x, v0.y, v0.z, v0.w, v1.x, v1.y, v1.z, v1.w};
        alignas(16) unsigned short hb[8];
        alignas(16) unsigned short lb[8];
#pragma unroll
        for (int q = 0; q < 8; ++q) {
            __nv_bfloat16 h = __float2bfloat16_rn(f[q]);
            hb[q] = bfbits(h);
            lb[q] = bfbits(__float2bfloat16_rn(f[q] - __bfloat162float(h)));
        }
        ((uint4*)hi)[i] = *(uint4*)hb;
        ((uint4*)lo)[i] = *(uint4*)lb;
    }
}

__global__ void deg_count(const void* __restrict__ ei, int E) {
    __shared__ int s64;
    int is64 = detect64_local(ei, &s64);
    int i = blockIdx.x * blockDim.x + threadIdx.x;
    if (i >= E) return;
    int d = is64 ? (int)((const long long*)ei)[(size_t)E + i]
                 : ((const int*)ei)[(size_t)E + i];
    atomicAdd(&d_degi[d], 1);
}

__global__ void __launch_bounds__(SCAN_T)
scan_partial(int n) {
    __shared__ int ssum[SCAN_T];
    const int tid  = threadIdx.x;
    const int base = blockIdx.x * SCAN_C + tid * 4;
    int v[4];
#pragma unroll
    for (int i = 0; i < 4; ++i) {
        v[i] = (base + i < n) ? d_degi[base + i] : 0;
        if (base + i < n) d_dinv[base + i] = rsqrtf((float)v[i] + 1.0f);
    }
    int tsum = v[0] + v[1] + v[2] + v[3];
    ssum[tid] = tsum;
    __syncthreads();
    for (int off = 1; off < SCAN_T; off <<= 1) {
        int t = (tid >= off) ? ssum[tid - off] : 0;
        __syncthreads();
        ssum[tid] += t;
        __syncthreads();
    }
    int texcl = ssum[tid] - tsum;
    if (tid == SCAN_T - 1) d_blocksums[blockIdx.x] = ssum[tid];
    int run = texcl;
#pragma unroll
    for (int i = 0; i < 4; ++i) {
        if (base + i < n) d_off[base + i] = run;
        run += v[i];
    }
}

__global__ void scan_blocksums(int nblk) {
    int tid = threadIdx.x;
    int v = (tid < nblk) ? d_blocksums[tid] : 0;
    int orig = v;
#pragma unroll
    for (int o = 1; o < 32; o <<= 1) {
        int t = __shfl_up_sync(0xFFFFFFFFu, v, o);
        if (tid >= o) v += t;
    }
    if (tid < nblk) d_blocksums[tid] = v - orig;
}

// scan_add also re-zeroes d_degi so the next graph replay sees zeros
// (replaces the critical-path memset).
__global__ void scan_add(int n, int E) {
    int i = blockIdx.x * blockDim.x + threadIdx.x;
    if (i < n) {
        int v = d_off[i] + d_blocksums[i / SCAN_C];
        d_off[i] = v;
        d_cursor[i] = v;
        d_degi[i] = 0;
    }
    if (i == 0) d_off[n] = E;
}

// scatter + W2 split into the W2-ONLY image buffers (no race with gemm1).
__global__ void scatter_ws(const void* __restrict__ ei, int E, int sblk,
                           const float* __restrict__ W2) {
    if (blockIdx.x >= sblk) {
        int idx = (blockIdx.x - sblk) * 256 + threadIdx.x;
        if (idx < 16384) w_split_elem(W2, d_W2hi, d_W2lo, idx);
        return;
    }
    __shared__ int s64;
    int is64 = detect64_local(ei, &s64);
    int i = blockIdx.x * blockDim.x + threadIdx.x;
    if (i >= E) return;
    int si, di;
    if (is64) {
        const long long* p = (const long long*)ei;
        si = (int)p[i];
        di = (int)p[(size_t)E + i];
    } else {
        const int* p = (const int*)ei;
        si = p[i];
        di = p[(size_t)E + i];
    }
    int pos = atomicAdd(&d_cursor[di], 1);
    d_csr[pos] = si;
}

// ---------------------------------------------------------------------------
// cp.async-pipelined persistent HMMA GEMM over tile range [t0, t1).
//   gout[row] = fp16( dinv[row] * (A[row] @ W) ),  A/W as bf16 hi/lo images.
__global__ void __launch_bounds__(256, 2)
gemm_tc(const unsigned short* __restrict__ Ahi,
        const unsigned short* __restrict__ Alo,
        const unsigned short* __restrict__ Whi,
        const unsigned short* __restrict__ Wlo,
        __half* __restrict__ gout, int n, int t0, int t1) {
    extern __shared__ char dsm[];
    char* sBh = dsm;
    char* sBl = dsm + B_SH;
    const uint32_t aBase = smem_u32(dsm + 2 * B_SH);

    const int tid = threadIdx.x;
    const int wid = tid >> 5;
    const int lid = tid & 31;

    {
        const float4* wh = (const float4*)Whi;
        const float4* wl = (const float4*)Wlo;
        float4* bh = (float4*)sBh;
        float4* bl = (float4*)sBl;
        for (int i = tid; i < B_SH / 16; i += 256) { bh[i] = wh[i]; bl[i] = wl[i]; }
    }

    const int mrow0 = (wid >> 2) * 16;
    const int ncol0 = (wid & 3) * 32;
    const int sel   = lid >> 3;
    const int rowIn = lid & 7;
    const uint32_t aoff =
        (uint32_t)(((mrow0 + rowIn + (sel & 1) * 8) * BSTRIDE + (sel >> 1) * 8) * 2);
    const uint32_t boff =
        (uint32_t)(((ncol0 + (sel >> 1) * 8 + rowIn) * BSTRIDE + (sel & 1) * 8) * 2);
    const uint32_t bHi = smem_u32(sBh) + boff;
    const uint32_t bLo = smem_u32(sBl) + boff;

    auto issue = [&](int tt, int s) {
#pragma unroll
        for (int i = 0; i < 4; ++i) {
            int id  = tid + i * 256;
            int img = id >> 9;
            int rc  = id & 511;
            int r   = rc >> 4;
            int c   = rc & 15;
            int gr  = tt * 32 + r;
            if (gr >= n) gr = n - 1;
            const unsigned short* src =
                (img ? Alo : Ahi) + (size_t)gr * FD + c * 8;
            uint32_t dst = aBase + s * (2 * A_STG) + img * A_STG +
                           r * (BSTRIDE * 2) + c * 16;
            cp16(dst, src);
        }
        asm volatile("cp.async.commit_group;" ::: "memory");
    };

    int t = t0 + blockIdx.x;
    if (t < t1) issue(t, 0);
    int p = 0;

    for (; t < t1; t += gridDim.x) {
        const int tn = t + gridDim.x;
        if (tn < t1) {
            issue(tn, p ^ 1);
            asm volatile("cp.async.wait_group 1;" ::: "memory");
        } else {
            asm volatile("cp.async.wait_group 0;" ::: "memory");
        }
        __syncthreads();

        const uint32_t aHi = aBase + p * (2 * A_STG) + aoff;
        const uint32_t aLo = aHi + A_STG;

        float acc[4][4];
#pragma unroll
        for (int j = 0; j < 4; ++j)
#pragma unroll
            for (int q = 0; q < 4; ++q) acc[j][q] = 0.f;

#pragma unroll
        for (int ks = 0; ks < 8; ++ks) {
            const uint32_t kb = ks * 32;
            uint32_t ah[4], al[4], bh2[4][2], bl2[4][2];
            ldm_x4(ah, aHi + kb);
            ldm_x4(al, aLo + kb);
#pragma unroll
            for (int j2 = 0; j2 < 2; ++j2) {
                uint32_t q[4];
                ldm_x4(q, bHi + j2 * (16 * BSTRIDE * 2) + kb);
                bh2[2 * j2][0] = q[0]; bh2[2 * j2][1] = q[1];
                bh2[2 * j2 + 1][0] = q[2]; bh2[2 * j2 + 1][1] = q[3];
                ldm_x4(q, bLo + j2 * (16 * BSTRIDE * 2) + kb);
                bl2[2 * j2][0] = q[0]; bl2[2 * j2][1] = q[1];
                bl2[2 * j2 + 1][0] = q[2]; bl2[2 * j2 + 1][1] = q[3];
            }
#pragma unroll
            for (int j = 0; j < 4; ++j) mma_bf16(acc[j], ah, bh2[j]);
#pragma unroll
            for (int j = 0; j < 4; ++j) mma_bf16(acc[j], ah, bl2[j]);
#pragma unroll
            for (int j = 0; j < 4; ++j) mma_bf16(acc[j], al, bh2[j]);
        }

        {
            const int r1 = t * 32 + mrow0 + (lid >> 2);
            const int r2 = r1 + 8;
            const int cbase = ncol0 + 2 * (lid & 3);
            const float dv1 = (r1 < n) ? d_dinv[r1] : 0.f;
            const float dv2 = (r2 < n) ? d_dinv[r2] : 0.f;
#pragma unroll
            for (int j = 0; j < 4; ++j) {
                int c = cbase + 8 * j;
                if (r1 < n)
                    *(__half2*)(gout + (size_t)r1 * FD + c) =
                        __floats2half2_rn(acc[j][0] * dv1, acc[j][1] * dv1);
                if (r2 < n)
                    *(__half2*)(gout + (size_t)r2 * FD + c) =
                        __floats2half2_rn(acc[j][2] * dv2, acc[j][3] * dv2);
            }
        }
        __syncthreads();
        p ^= 1;
    }
}

// ---------------------------------------------------------------------------
// Fused aggregate over nodes [w0, w0+cnt): warp per node, fp16 gather.
//   out[d] = dinv[d]*(Σ g[s] + g[d]) + b
// mode 1: relu, write h as bf16 hi/lo images. mode 0: write fp32 out.
__global__ void __launch_bounds__(256)
aggregate_csr(const __half* __restrict__ g, const float* __restrict__ bias,
              float* __restrict__ out, unsigned short* __restrict__ ohi,
              unsigned short* __restrict__ olo, int w0, int cnt, int mode) {
    const int w = w0 + blockIdx.x * 8 + (threadIdx.x >> 5);
    if (w >= w0 + cnt) return;
    const int lane = threadIdx.x & 31;

    const uint2* gw = (const uint2*)g + lane;

    float acc0, acc1, acc2, acc3;
    {
        uint2 raw = __ldg(gw + (size_t)w * 32);
        float2 f0 = __half22float2(*(__half2*)&raw.x);
        float2 f1 = __half22float2(*(__half2*)&raw.y);
        acc0 = f0.x; acc1 = f0.y; acc2 = f1.x; acc3 = f1.y;
    }

    int e = d_off[w];
    const int eend = d_off[w + 1];
    for (; e + 4 <= eend; e += 4) {
        int s0 = __ldg(&d_csr[e]);
        int s1 = __ldg(&d_csr[e + 1]);
        int s2 = __ldg(&d_csr[e + 2]);
        int s3 = __ldg(&d_csr[e + 3]);
        uint2 ra = __ldg(gw + (size_t)s0 * 32);
        uint2 rb = __ldg(gw + (size_t)s1 * 32);
        uint2 rc = __ldg(gw + (size_t)s2 * 32);
        uint2 rd = __ldg(gw + (size_t)s3 * 32);
        float2 a0 = __half22float2(*(__half2*)&ra.x), a1 = __half22float2(*(__half2*)&ra.y);
        float2 b0 = __half22float2(*(__half2*)&rb.x), b1 = __half22float2(*(__half2*)&rb.y);
        float2 c0 = __half22float2(*(__half2*)&rc.x), c1 = __half22float2(*(__half2*)&rc.y);
        float2 d0 = __half22float2(*(__half2*)&rd.x), d1 = __half22float2(*(__half2*)&rd.y);
        acc0 += (a0.x + b0.x) + (c0.x + d0.x);
        acc1 += (a0.y + b0.y) + (c0.y + d0.y);
        acc2 += (a1.x + b1.x) + (c1.x + d1.x);
        acc3 += (a1.y + b1.y) + (c1.y + d1.y);
    }
    for (; e < eend; ++e) {
        int s0 = __ldg(&d_csr[e]);
        uint2 ra = __ldg(gw + (size_t)s0 * 32);
        float2 a0 = __half22float2(*(__half2*)&ra.x), a1 = __half22float2(*(__half2*)&ra.y);
        acc0 += a0.x; acc1 += a0.y; acc2 += a1.x; acc3 += a1.y;
    }

    const float dv = d_dinv[w];
    float4 bs = __ldg((const float4*)bias + lane);
    float r0 = dv * acc0 + bs.x;
    float r1 = dv * acc1 + bs.y;
    float r2 = dv * acc2 + bs.z;
    float r3 = dv * acc3 + bs.w;

    if (mode) {
        r0 = fmaxf(r0, 0.f); r1 = fmaxf(r1, 0.f);
        r2 = fmaxf(r2, 0.f); r3 = fmaxf(r3, 0.f);
        float f[4] = {r0, r1, r2, r3};
        alignas(8) unsigned short hb[4];
        alignas(8) unsigned short lb[4];
#pragma unroll
        for (int q = 0; q < 4; ++q) {
            __nv_bfloat16 h = __float2bfloat16_rn(f[q]);
            hb[q] = bfbits(h);
            lb[q] = bfbits(__float2bfloat16_rn(f[q] - __bfloat162float(h)));
        }
        *(uint2*)(ohi + (size_t)w * FD + lane * 4) = *(uint2*)hb;
        *(uint2*)(olo + (size_t)w * FD + lane * 4) = *(uint2*)lb;
    } else {
        ((float4*)(out + (size_t)w * FD))[lane] = make_float4(r0, r1, r2, r3);
    }
}

// ---------------------------------------------------------------------------
extern "C" void kernel_launch(void* const* d_in, const int* in_sizes, int n_in,
                              void* d_out, int out_size) {
    const float* x  = (const float*)d_in[0];
    const void*  ei = d_in[1];
    const float* W1 = (const float*)d_in[2];
    const float* b1 = (const float*)d_in[3];
    const float* W2 = (const float*)d_in[4];
    const float* b2 = (const float*)d_in[5];
    float* out = (float*)d_out;

    int n = in_sizes[0] / FD;
    if (n > NMAX) n = NMAX;
    int E = in_sizes[1] / 2;
    if (E > EMAX) E = EMAX;

    float* bufA;
    unsigned short *xhi, *xlo, *hhi, *hlo, *w1hi, *w1lo, *w2hi, *w2lo;
    cudaGetSymbolAddress((void**)&bufA, d_bufA);
    cudaGetSymbolAddress((void**)&xhi, d_xhi);
    cudaGetSymbolAddress((void**)&xlo, d_xlo);
    cudaGetSymbolAddress((void**)&hhi, d_hhi);
    cudaGetSymbolAddress((void**)&hlo, d_hlo);
    cudaGetSymbolAddress((void**)&w1hi, d_W1hi);
    cudaGetSymbolAddress((void**)&w1lo, d_W1lo);
    cudaGetSymbolAddress((void**)&w2hi, d_W2hi);
    cudaGetSymbolAddress((void**)&w2lo, d_W2lo);
    __half* gbuf = (__half*)bufA;

    cudaFuncSetAttribute(gemm_tc,
                         cudaFuncAttributeMaxDynamicSharedMemorySize, GEMM_SMEM);

    static cudaStream_t s_side = []() {
        cudaStream_t s;
        cudaStreamCreateWithFlags(&s, cudaStreamNonBlocking);
        return s;
    }();
    static cudaEvent_t ev[5] = {};
    if (!ev[0])
        for (int i = 0; i < 5; ++i)
            cudaEventCreateWithFlags(&ev[i], cudaEventDisableTiming);
    cudaEvent_t e_fork = ev[0], e_dinv = ev[1], e_csr = ev[2],
                e_h1 = ev[3], e_g2 = ev[4];

    const int ntiles = (n + 31) / 32;
    const int tilesA = ntiles / 2;         // chunk 1 tiles
    const int n1 = tilesA * 32;            // chunk 1 rows
    const int ggrid = (ntiles < 2 * NSM) ? ntiles : 2 * NSM;
    const int gA = (tilesA < 2 * NSM) ? (tilesA > 0 ? tilesA : 1) : 2 * NSM;
    const int gB = ((ntiles - tilesA) < 2 * NSM) ? (ntiles - tilesA) : 2 * NSM;
    const int sblk = (E + 255) / 256;

    // ---- fork: degree/dinv + CSR + W2 split on side stream ----
    cudaEventRecord(e_fork, 0);
    cudaStreamWaitEvent(s_side, e_fork, 0);
    deg_count<<<(E + 255) / 256, 256, 0, s_side>>>(ei, E);
    scan_partial<<<SCAN_NBLK, SCAN_T, 0, s_side>>>(n);   // produces dinv
    cudaEventRecord(e_dinv, s_side);
    scan_blocksums<<<1, 32, 0, s_side>>>(SCAN_NBLK);
    scan_add<<<(n + 255) / 256, 256, 0, s_side>>>(n, E); // re-zeroes degi
    scatter_ws<<<sblk + 64, 256, 0, s_side>>>(ei, E, sblk, W2);
    cudaEventRecord(e_csr, s_side);

    // ---- main: fused W1+x split; gemm1 waits only for dinv ----
    split_all<<<64 + 2 * NSM, 256>>>(x, W1, xhi, xlo, n * 16);
    cudaStreamWaitEvent(0, e_dinv, 0);
    gemm_tc<<<ggrid, 256, GEMM_SMEM>>>(xhi, xlo, w1hi, w1lo, gbuf, n, 0, ntiles);

    // ---- agg1 / gemm2 software pipeline (2 chunks) ----
    cudaStreamWaitEvent(0, e_csr, 0);
    aggregate_csr<<<(n1 + 7) / 8, 256>>>(gbuf, b1, nullptr, hhi, hlo, 0, n1, 1);
    cudaEventRecord(e_h1, 0);
    aggregate_csr<<<(n - n1 + 7) / 8, 256>>>(gbuf, b1, nullptr, hhi, hlo,
                                             n1, n - n1, 1);

    // gemm2 chunk 1 on side stream, overlapping agg1 chunk 2
    cudaStreamWaitEvent(s_side, e_h1, 0);
    gemm_tc<<<gA, 256, GEMM_SMEM, s_side>>>(hhi, hlo, w2hi, w2lo, gbuf,
                                            n, 0, tilesA);
    cudaEventRecord(e_g2, s_side);

    // gemm2 chunk 2 on main (after agg1 chunk 2, stream-ordered)
    gemm_tc<<<gB, 256, GEMM_SMEM>>>(hhi, hlo, w2hi, w2lo, gbuf,
                                    n, tilesA, ntiles);

    // ---- agg2 needs both gemm2 chunks ----
    cudaStreamWaitEvent(0, e_g2, 0);
    aggregate_csr<<<(n + 7) / 8, 256>>>(gbuf, b2, out, nullptr, nullptr,
                                        0, n, 0);
}

// round 16
// speedup vs baseline: 1.0928x; 1.0928x over previous
#include <cuda_runtime.h>
#include <cuda_fp16.h>
#include <cstdint>

// GNN_9869834846215: two-layer cached GCN.
//   g = dinv ⊙ (h W) (fp16)  -- cp.async-pipelined fp16 HMMA, W split hi/lo
//   out[d] = dinv[d]*(Σ_{s∈N(d)} g[s] + g[d]) + b
// A operands (x, h) stored as single fp16 images; W as fp16 hi+lo (22-bit).

#define NMAX 100000
#define EMAX 1700000
#define FD 128
#define SCAN_T 1024
#define SCAN_C 4096
#define SCAN_NBLK 25
#define NSM 148

#define BSTRIDE 136                        // fp16 smem row stride (272B)
#define B_SH (128 * BSTRIDE * 2)           // 34816 B per W image
#define A_STG (32 * BSTRIDE * 2)           // 8704 B per 32-row A image
#define GEMM_SMEM (2 * B_SH + 2 * A_STG)   // 87040 -> 2 blocks/SM

// Scratch (__device__ globals; d_degi zero-init, re-zeroed by scan_add)
__device__ float d_dinv[NMAX];
__device__ float d_bufA[(size_t)NMAX * FD];            // g (fp16 view)
__device__ __align__(16) unsigned short d_xh[(size_t)NMAX * FD];  // x fp16
__device__ __align__(16) unsigned short d_hh[(size_t)NMAX * FD];  // h fp16
__device__ int   d_degi[NMAX];
__device__ int   d_off[NMAX + 1];
__device__ int   d_cursor[NMAX];
__device__ int   d_csr[EMAX];
__device__ int   d_blocksums[32];
// W^T fp16 hi/lo images ([n][k], row stride BSTRIDE)
__device__ __align__(16) unsigned short d_W1hi[128 * BSTRIDE];
__device__ __align__(16) unsigned short d_W1lo[128 * BSTRIDE];
__device__ __align__(16) unsigned short d_W2hi[128 * BSTRIDE];
__device__ __align__(16) unsigned short d_W2lo[128 * BSTRIDE];

// ---------------------------------------------------------------------------
__device__ __forceinline__ uint32_t smem_u32(const void* p) {
    uint32_t a;
    asm("{ .reg .u64 t; cvta.to.shared.u64 t, %1; cvt.u32.u64 %0, t; }"
        : "=r"(a) : "l"(p));
    return a;
}
__device__ __forceinline__ void ldm_x4(uint32_t* r, uint32_t addr) {
    asm volatile("ldmatrix.sync.aligned.m8n8.x4.shared.b16 {%0,%1,%2,%3}, [%4];"
                 : "=r"(r[0]), "=r"(r[1]), "=r"(r[2]), "=r"(r[3]) : "r"(addr));
}
__device__ __forceinline__ void mma_f16(float* c, const uint32_t* a,
                                        const uint32_t* b) {
    asm volatile(
        "mma.sync.aligned.m16n8k16.row.col.f32.f16.f16.f32 "
        "{%0,%1,%2,%3}, {%4,%5,%6,%7}, {%8,%9}, {%0,%1,%2,%3};"
        : "+f"(c[0]), "+f"(c[1]), "+f"(c[2]), "+f"(c[3])
        : "r"(a[0]), "r"(a[1]), "r"(a[2]), "r"(a[3]), "r"(b[0]), "r"(b[1]));
}
__device__ __forceinline__ void cp16(uint32_t smem, const void* g) {
    asm volatile("cp.async.cg.shared.global [%0], [%1], 16;"
                 :: "r"(smem), "l"(g) : "memory");
}
__device__ __forceinline__ unsigned short hbits(__half h) {
    return __half_as_ushort(h);
}
__device__ __forceinline__ int detect64_local(const void* ei, int* s64) {
    if (threadIdx.x == 0) {
        const int2* p = (const int2*)ei;
        int is64 = 1;
        for (int j = 0; j < 64; ++j)
            if (p[j].y != 0) { is64 = 0; break; }
        *s64 = is64;
    }
    __syncthreads();
    return *s64;
}

// ---------------------------------------------------------------------------
// Split one W element into fp16 hi/lo images. B[n][k] = W[k][n].
__device__ __forceinline__ void w_split_elem(const float* W,
                                             unsigned short* hi,
                                             unsigned short* lo, int idx) {
    int nn = idx & 127, kk = idx >> 7;
    float v = W[kk * FD + nn];
    __half h = __float2half_rn(v);
    __half l = __float2half_rn(v - __half2float(h));
    hi[nn * BSTRIDE + kk] = hbits(h);
    lo[nn * BSTRIDE + kk] = hbits(l);
}

// Fused prepass: blocks [0,64) split W1; blocks [64,..) convert x to fp16.
__global__ void split_all(const float* __restrict__ x,
                          const float* __restrict__ W1,
                          unsigned short* __restrict__ xh, int total8) {
    if (blockIdx.x < 64) {
        int idx = blockIdx.x * 256 + threadIdx.x;
        if (idx < 16384) w_split_elem(W1, d_W1hi, d_W1lo, idx);
        return;
    }
    const int nb = gridDim.x - 64;
    for (int i = (blockIdx.x - 64) * blockDim.x + threadIdx.x; i < total8;
         i += nb * blockDim.x) {
        const float4* src = (const float4*)x + 2 * (size_t)i;
        float4 v0 = __ldg(src);
        float4 v1 = __ldg(src + 1);
        alignas(16) unsigned short hb[8];
        hb[0] = hbits(__float2half_rn(v0.x));
        hb[1] = hbits(__float2half_rn(v0.y));
        hb[2] = hbits(__float2half_rn(v0.z));
        hb[3] = hbits(__float2half_rn(v0.w));
        hb[4] = hbits(__float2half_rn(v1.x));
        hb[5] = hbits(__float2half_rn(v1.y));
        hb[6] = hbits(__float2half_rn(v1.z));
        hb[7] = hbits(__float2half_rn(v1.w));
        ((uint4*)xh)[i] = *(uint4*)hb;
    }
}

__global__ void deg_count(const void* __restrict__ ei, int E) {
    __shared__ int s64;
    int is64 = detect64_local(ei, &s64);
    int i = blockIdx.x * blockDim.x + threadIdx.x;
    if (i >= E) return;
    int d = is64 ? (int)((const long long*)ei)[(size_t)E + i]
                 : ((const int*)ei)[(size_t)E + i];
    atomicAdd(&d_degi[d], 1);
}

__global__ void __launch_bounds__(SCAN_T)
scan_partial(int n) {
    __shared__ int ssum[SCAN_T];
    const int tid  = threadIdx.x;
    const int base = blockIdx.x * SCAN_C + tid * 4;
    int v[4];
#pragma unroll
    for (int i = 0; i < 4; ++i) {
        v[i] = (base + i < n) ? d_degi[base + i] : 0;
        if (base + i < n) d_dinv[base + i] = rsqrtf((float)v[i] + 1.0f);
    }
    int tsum = v[0] + v[1] + v[2] + v[3];
    ssum[tid] = tsum;
    __syncthreads();
    for (int off = 1; off < SCAN_T; off <<= 1) {
        int t = (tid >= off) ? ssum[tid - off] : 0;
        __syncthreads();
        ssum[tid] += t;
        __syncthreads();
    }
    int texcl = ssum[tid] - tsum;
    if (tid == SCAN_T - 1) d_blocksums[blockIdx.x] = ssum[tid];
    int run = texcl;
#pragma unroll
    for (int i = 0; i < 4; ++i) {
        if (base + i < n) d_off[base + i] = run;
        run += v[i];
    }
}

__global__ void scan_blocksums(int nblk) {
    int tid = threadIdx.x;
    int v = (tid < nblk) ? d_blocksums[tid] : 0;
    int orig = v;
#pragma unroll
    for (int o = 1; o < 32; o <<= 1) {
        int t = __shfl_up_sync(0xFFFFFFFFu, v, o);
        if (tid >= o) v += t;
    }
    if (tid < nblk) d_blocksums[tid] = v - orig;
}

// scan_add also re-zeroes d_degi for the next graph replay.
__global__ void scan_add(int n, int E) {
    int i = blockIdx.x * blockDim.x + threadIdx.x;
    if (i < n) {
        int v = d_off[i] + d_blocksums[i / SCAN_C];
        d_off[i] = v;
        d_cursor[i] = v;
        d_degi[i] = 0;
    }
    if (i == 0) d_off[n] = E;
}

// scatter + W2 split into the W2-ONLY image buffers (no race with gemm1).
__global__ void scatter_ws(const void* __restrict__ ei, int E, int sblk,
                           const float* __restrict__ W2) {
    if (blockIdx.x >= sblk) {
        int idx = (blockIdx.x - sblk) * 256 + threadIdx.x;
        if (idx < 16384) w_split_elem(W2, d_W2hi, d_W2lo, idx);
        return;
    }
    __shared__ int s64;
    int is64 = detect64_local(ei, &s64);
    int i = blockIdx.x * blockDim.x + threadIdx.x;
    if (i >= E) return;
    int si, di;
    if (is64) {
        const long long* p = (const long long*)ei;
        si = (int)p[i];
        di = (int)p[(size_t)E + i];
    } else {
        const int* p = (const int*)ei;
        si = p[i];
        di = p[(size_t)E + i];
    }
    int pos = atomicAdd(&d_cursor[di], 1);
    d_csr[pos] = si;
}

// ---------------------------------------------------------------------------
// cp.async-pipelined persistent fp16 HMMA GEMM (2-term: A·Whi + A·Wlo).
//   gout[row] = fp16( dinv[row] * (A[row] @ W) ),  A single fp16 image.
// 32-row tiles, warp tile 16x32, 2-stage A ring, 2 blocks/SM.
__global__ void __launch_bounds__(256, 2)
gemm_tc(const unsigned short* __restrict__ Ah,
        const unsigned short* __restrict__ Whi,
        const unsigned short* __restrict__ Wlo,
        __half* __restrict__ gout, int n, int ntiles) {
    extern __shared__ char dsm[];
    char* sBh = dsm;
    char* sBl = dsm + B_SH;
    const uint32_t aBase = smem_u32(dsm + 2 * B_SH);   // 2 stages

    const int tid = threadIdx.x;
    const int wid = tid >> 5;
    const int lid = tid & 31;

    // Stage W images once (linear copy).
    {
        const float4* wh = (const float4*)Whi;
        const float4* wl = (const float4*)Wlo;
        float4* bh = (float4*)sBh;
        float4* bl = (float4*)sBl;
        for (int i = tid; i < B_SH / 16; i += 256) { bh[i] = wh[i]; bl[i] = wl[i]; }
    }

    // Warp tiling: 16 rows x 32 cols.
    const int mrow0 = (wid >> 2) * 16;     // 0 or 16
    const int ncol0 = (wid & 3) * 32;      // 0,32,64,96
    const int sel   = lid >> 3;
    const int rowIn = lid & 7;
    const uint32_t aoff =
        (uint32_t)(((mrow0 + rowIn + (sel & 1) * 8) * BSTRIDE + (sel >> 1) * 8) * 2);
    const uint32_t boff =
        (uint32_t)(((ncol0 + (sel >> 1) * 8 + rowIn) * BSTRIDE + (sel & 1) * 8) * 2);
    const uint32_t bHi = smem_u32(sBh) + boff;
    const uint32_t bLo = smem_u32(sBl) + boff;

    // cp.async: 512 chunks = 32 rows x 16 chunks(16B). 2 per thread.
    auto issue = [&](int tt, int s) {
#pragma unroll
        for (int i = 0; i < 2; ++i) {
            int id = tid + i * 256;
            int r  = id >> 4;
            int c  = id & 15;
            int gr = tt * 32 + r;
            if (gr >= n) gr = n - 1;
            const unsigned short* src = Ah + (size_t)gr * FD + c * 8;
            uint32_t dst = aBase + s * A_STG + r * (BSTRIDE * 2) + c * 16;
            cp16(dst, src);
        }
        asm volatile("cp.async.commit_group;" ::: "memory");
    };

    int t = blockIdx.x;
    if (t < ntiles) issue(t, 0);
    int p = 0;

    for (; t < ntiles; t += gridDim.x) {
        const int tn = t + gridDim.x;
        if (tn < ntiles) {
            issue(tn, p ^ 1);
            asm volatile("cp.async.wait_group 1;" ::: "memory");
        } else {
            asm volatile("cp.async.wait_group 0;" ::: "memory");
        }
        __syncthreads();

        const uint32_t aB = aBase + p * A_STG + aoff;

        float acc[4][4];
#pragma unroll
        for (int j = 0; j < 4; ++j)
#pragma unroll
            for (int q = 0; q < 4; ++q) acc[j][q] = 0.f;

#pragma unroll
        for (int ks = 0; ks < 8; ++ks) {
            const uint32_t kb = ks * 32;
            uint32_t a[4], bh2[4][2], bl2[4][2];
            ldm_x4(a, aB + kb);
#pragma unroll
            for (int j2 = 0; j2 < 2; ++j2) {
                uint32_t q[4];
                ldm_x4(q, bHi + j2 * (16 * BSTRIDE * 2) + kb);
                bh2[2 * j2][0] = q[0]; bh2[2 * j2][1] = q[1];
                bh2[2 * j2 + 1][0] = q[2]; bh2[2 * j2 + 1][1] = q[3];
                ldm_x4(q, bLo + j2 * (16 * BSTRIDE * 2) + kb);
                bl2[2 * j2][0] = q[0]; bl2[2 * j2][1] = q[1];
                bl2[2 * j2 + 1][0] = q[2]; bl2[2 * j2 + 1][1] = q[3];
            }
#pragma unroll
            for (int j = 0; j < 4; ++j) mma_f16(acc[j], a, bh2[j]);
#pragma unroll
            for (int j = 0; j < 4; ++j) mma_f16(acc[j], a, bl2[j]);
        }

        // Epilogue: scale by dinv[row], convert fp16, store.
        {
            const int r1 = t * 32 + mrow0 + (lid >> 2);
            const int r2 = r1 + 8;
            const int cbase = ncol0 + 2 * (lid & 3);
            const float dv1 = (r1 < n) ? d_dinv[r1] : 0.f;
            const float dv2 = (r2 < n) ? d_dinv[r2] : 0.f;
#pragma unroll
            for (int j = 0; j < 4; ++j) {
                int c = cbase + 8 * j;
                if (r1 < n)
                    *(__half2*)(gout + (size_t)r1 * FD + c) =
                        __floats2half2_rn(acc[j][0] * dv1, acc[j][1] * dv1);
                if (r2 < n)
                    *(__half2*)(gout + (size_t)r2 * FD + c) =
                        __floats2half2_rn(acc[j][2] * dv2, acc[j][3] * dv2);
            }
        }
        __syncthreads();
        p ^= 1;
    }
}

// ---------------------------------------------------------------------------
// Fused aggregate: one warp per dst node, fp16 gather (g pre-scaled by dinv).
//   out[d] = dinv[d]*(Σ g[s] + g[d]) + b
// mode 1: relu, write h as single fp16 image. mode 0: write fp32 out.
__global__ void __launch_bounds__(256)
aggregate_csr(const __half* __restrict__ g, const float* __restrict__ bias,
              float* __restrict__ out, unsigned short* __restrict__ oh,
              int n, int mode) {
    const int w = blockIdx.x * 8 + (threadIdx.x >> 5);
    if (w >= n) return;
    const int lane = threadIdx.x & 31;

    const uint2* gw = (const uint2*)g + lane;

    float acc0, acc1, acc2, acc3;
    {
        uint2 raw = __ldg(gw + (size_t)w * 32);
        float2 f0 = __half22float2(*(__half2*)&raw.x);
        float2 f1 = __half22float2(*(__half2*)&raw.y);
        acc0 = f0.x; acc1 = f0.y; acc2 = f1.x; acc3 = f1.y;
    }

    int e = d_off[w];
    const int eend = d_off[w + 1];
    for (; e + 4 <= eend; e += 4) {
        int s0 = __ldg(&d_csr[e]);
        int s1 = __ldg(&d_csr[e + 1]);
        int s2 = __ldg(&d_csr[e + 2]);
        int s3 = __ldg(&d_csr[e + 3]);
        uint2 ra = __ldg(gw + (size_t)s0 * 32);
        uint2 rb = __ldg(gw + (size_t)s1 * 32);
        uint2 rc = __ldg(gw + (size_t)s2 * 32);
        uint2 rd = __ldg(gw + (size_t)s3 * 32);
        float2 a0 = __half22float2(*(__half2*)&ra.x), a1 = __half22float2(*(__half2*)&ra.y);
        float2 b0 = __half22float2(*(__half2*)&rb.x), b1 = __half22float2(*(__half2*)&rb.y);
        float2 c0 = __half22float2(*(__half2*)&rc.x), c1 = __half22float2(*(__half2*)&rc.y);
        float2 d0 = __half22float2(*(__half2*)&rd.x), d1 = __half22float2(*(__half2*)&rd.y);
        acc0 += (a0.x + b0.x) + (c0.x + d0.x);
        acc1 += (a0.y + b0.y) + (c0.y + d0.y);
        acc2 += (a1.x + b1.x) + (c1.x + d1.x);
        acc3 += (a1.y + b1.y) + (c1.y + d1.y);
    }
    for (; e < eend; ++e) {
        int s0 = __ldg(&d_csr[e]);
        uint2 ra = __ldg(gw + (size_t)s0 * 32);
        float2 a0 = __half22float2(*(__half2*)&ra.x), a1 = __half22float2(*(__half2*)&ra.y);
        acc0 += a0.x; acc1 += a0.y; acc2 += a1.x; acc3 += a1.y;
    }

    const float dv = d_dinv[w];
    float4 bs = __ldg((const float4*)bias + lane);
    float r0 = dv * acc0 + bs.x;
    float r1 = dv * acc1 + bs.y;
    float r2 = dv * acc2 + bs.z;
    float r3 = dv * acc3 + bs.w;

    if (mode) {
        r0 = fmaxf(r0, 0.f); r1 = fmaxf(r1, 0.f);
        r2 = fmaxf(r2, 0.f); r3 = fmaxf(r3, 0.f);
        alignas(8) unsigned short hb[4];
        hb[0] = hbits(__float2half_rn(r0));
        hb[1] = hbits(__float2half_rn(r1));
        hb[2] = hbits(__float2half_rn(r2));
        hb[3] = hbits(__float2half_rn(r3));
        *(uint2*)(oh + (size_t)w * FD + lane * 4) = *(uint2*)hb;
    } else {
        ((float4*)(out + (size_t)w * FD))[lane] = make_float4(r0, r1, r2, r3);
    }
}

// ---------------------------------------------------------------------------
extern "C" void kernel_launch(void* const* d_in, const int* in_sizes, int n_in,
                              void* d_out, int out_size) {
    const float* x  = (const float*)d_in[0];
    const void*  ei = d_in[1];
    const float* W1 = (const float*)d_in[2];
    const float* b1 = (const float*)d_in[3];
    const float* W2 = (const float*)d_in[4];
    const float* b2 = (const float*)d_in[5];
    float* out = (float*)d_out;

    int n = in_sizes[0] / FD;
    if (n > NMAX) n = NMAX;
    int E = in_sizes[1] / 2;
    if (E > EMAX) E = EMAX;

    float* bufA;
    unsigned short *xh, *hh, *w1hi, *w1lo, *w2hi, *w2lo;
    cudaGetSymbolAddress((void**)&bufA, d_bufA);
    cudaGetSymbolAddress((void**)&xh, d_xh);
    cudaGetSymbolAddress((void**)&hh, d_hh);
    cudaGetSymbolAddress((void**)&w1hi, d_W1hi);
    cudaGetSymbolAddress((void**)&w1lo, d_W1lo);
    cudaGetSymbolAddress((void**)&w2hi, d_W2hi);
    cudaGetSymbolAddress((void**)&w2lo, d_W2lo);
    __half* gbuf = (__half*)bufA;

    cudaFuncSetAttribute(gemm_tc,
                         cudaFuncAttributeMaxDynamicSharedMemorySize, GEMM_SMEM);

    static cudaStream_t s_side = []() {
        cudaStream_t s;
        cudaStreamCreateWithFlags(&s, cudaStreamNonBlocking);
        return s;
    }();
    static cudaEvent_t ev[3] = {};
    if (!ev[0])
        for (int i = 0; i < 3; ++i)
            cudaEventCreateWithFlags(&ev[i], cudaEventDisableTiming);
    cudaEvent_t e_fork = ev[0], e_dinv = ev[1], e_csr = ev[2];

    const int ntiles = (n + 31) / 32;
    const int ggrid = (ntiles < 2 * NSM) ? ntiles : 2 * NSM;
    const int sblk = (E + 255) / 256;

    // ---- fork: degree/dinv + CSR + W2 split on side stream ----
    cudaEventRecord(e_fork, 0);
    cudaStreamWaitEvent(s_side, e_fork, 0);
    deg_count<<<(E + 255) / 256, 256, 0, s_side>>>(ei, E);
    scan_partial<<<SCAN_NBLK, SCAN_T, 0, s_side>>>(n);   // produces dinv
    cudaEventRecord(e_dinv, s_side);
    scan_blocksums<<<1, 32, 0, s_side>>>(SCAN_NBLK);
    scan_add<<<(n + 255) / 256, 256, 0, s_side>>>(n, E); // re-zeroes degi
    scatter_ws<<<sblk + 64, 256, 0, s_side>>>(ei, E, sblk, W2);
    cudaEventRecord(e_csr, s_side);

    // ---- main: fused W1 split + x->fp16; gemm1 waits only for dinv ----
    split_all<<<64 + 2 * NSM, 256>>>(x, W1, xh, n * 16);
    cudaStreamWaitEvent(0, e_dinv, 0);
    gemm_tc<<<ggrid, 256, GEMM_SMEM>>>(xh, w1hi, w1lo, gbuf, n, ntiles);

    // ---- join CSR; aggregate 1 (relu, h fp16) ----
    cudaStreamWaitEvent(0, e_csr, 0);
    aggregate_csr<<<(n + 7) / 8, 256>>>(gbuf, b1, nullptr, hh, n, 1);

    // ---- layer 2 ----
    gemm_tc<<<ggrid, 256, GEMM_SMEM>>>(hh, w2hi, w2lo, gbuf, n, ntiles);
    aggregate_csr<<<(n + 7) / 8, 256>>>(gbuf, b2, out, nullptr, n, 0);
}

// round 17
// speedup vs baseline: 1.1450x; 1.0477x over previous
#include <cuda_runtime.h>
#include <cuda_fp16.h>
#include <cstdint>

// GNN_9869834846215: two-layer cached GCN.
//   g = dinv ⊙ (h W) (fp16)  -- cp.async-pipelined pure-fp16 HMMA GEMM
//   out[d] = dinv[d]*(Σ_{s∈N(d)} g[s] + g[d]) + b
// All GEMM operands single fp16 images (precision budget: ~5e-4 << 1e-3).

#define NMAX 100000
#define EMAX 1700000
#define FD 128
#define SCAN_T 1024
#define SCAN_C 4096
#define SCAN_NBLK 25
#define NSM 148

#define BSTRIDE 136                        // fp16 smem row stride (272B)
#define B_SH (128 * BSTRIDE * 2)           // 34816 B (W image)
#define A_STG (32 * BSTRIDE * 2)           // 8704 B per 32-row A image
#define GEMM_SMEM (B_SH + 2 * A_STG)       // 52224 -> 3 blocks/SM

// Scratch (__device__ globals; d_degi zero-init, re-zeroed by scan_add)
__device__ float d_dinv[NMAX];
__device__ float d_bufA[(size_t)NMAX * FD];            // g (fp16 view)
__device__ __align__(16) unsigned short d_xh[(size_t)NMAX * FD];  // x fp16
__device__ __align__(16) unsigned short d_hh[(size_t)NMAX * FD];  // h fp16
__device__ int   d_degi[NMAX];
__device__ int   d_off[NMAX + 1];
__device__ int   d_cursor[NMAX];
__device__ int   d_csr[EMAX];
__device__ int   d_blocksums[32];
// W^T fp16 images ([n][k], row stride BSTRIDE)
__device__ __align__(16) unsigned short d_W1h[128 * BSTRIDE];
__device__ __align__(16) unsigned short d_W2h[128 * BSTRIDE];

// ---------------------------------------------------------------------------
__device__ __forceinline__ uint32_t smem_u32(const void* p) {
    uint32_t a;
    asm("{ .reg .u64 t; cvta.to.shared.u64 t, %1; cvt.u32.u64 %0, t; }"
        : "=r"(a) : "l"(p));
    return a;
}
__device__ __forceinline__ void ldm_x4(uint32_t* r, uint32_t addr) {
    asm volatile("ldmatrix.sync.aligned.m8n8.x4.shared.b16 {%0,%1,%2,%3}, [%4];"
                 : "=r"(r[0]), "=r"(r[1]), "=r"(r[2]), "=r"(r[3]) : "r"(addr));
}
__device__ __forceinline__ void mma_f16(float* c, const uint32_t* a,
                                        const uint32_t* b) {
    asm volatile(
        "mma.sync.aligned.m16n8k16.row.col.f32.f16.f16.f32 "
        "{%0,%1,%2,%3}, {%4,%5,%6,%7}, {%8,%9}, {%0,%1,%2,%3};"
        : "+f"(c[0]), "+f"(c[1]), "+f"(c[2]), "+f"(c[3])
        : "r"(a[0]), "r"(a[1]), "r"(a[2]), "r"(a[3]), "r"(b[0]), "r"(b[1]));
}
__device__ __forceinline__ void cp16(uint32_t smem, const void* g) {
    asm volatile("cp.async.cg.shared.global [%0], [%1], 16;"
                 :: "r"(smem), "l"(g) : "memory");
}
__device__ __forceinline__ unsigned short hbits(__half h) {
    return __half_as_ushort(h);
}
__device__ __forceinline__ int detect64_local(const void* ei, int* s64) {
    if (threadIdx.x == 0) {
        const int2* p = (const int2*)ei;
        int is64 = 1;
        for (int j = 0; j < 64; ++j)
            if (p[j].y != 0) { is64 = 0; break; }
        *s64 = is64;
    }
    __syncthreads();
    return *s64;
}

// ---------------------------------------------------------------------------
// Convert one W element into the fp16 image. B[n][k] = W[k][n].
__device__ __forceinline__ void w_conv_elem(const float* W,
                                            unsigned short* img, int idx) {
    int nn = idx & 127, kk = idx >> 7;
    img[nn * BSTRIDE + kk] = hbits(__float2half_rn(W[kk * FD + nn]));
}

// Fused prepass: blocks [0,64) convert W1; blocks [64,..) convert x to fp16.
__global__ void split_all(const float* __restrict__ x,
                          const float* __restrict__ W1,
                          unsigned short* __restrict__ xh, int total8) {
    if (blockIdx.x < 64) {
        int idx = blockIdx.x * 256 + threadIdx.x;
        if (idx < 16384) w_conv_elem(W1, d_W1h, idx);
        return;
    }
    const int nb = gridDim.x - 64;
    for (int i = (blockIdx.x - 64) * blockDim.x + threadIdx.x; i < total8;
         i += nb * blockDim.x) {
        const float4* src = (const float4*)x + 2 * (size_t)i;
        float4 v0 = __ldg(src);
        float4 v1 = __ldg(src + 1);
        alignas(16) unsigned short hb[8];
        hb[0] = hbits(__float2half_rn(v0.x));
        hb[1] = hbits(__float2half_rn(v0.y));
        hb[2] = hbits(__float2half_rn(v0.z));
        hb[3] = hbits(__float2half_rn(v0.w));
        hb[4] = hbits(__float2half_rn(v1.x));
        hb[5] = hbits(__float2half_rn(v1.y));
        hb[6] = hbits(__float2half_rn(v1.z));
        hb[7] = hbits(__float2half_rn(v1.w));
        ((uint4*)xh)[i] = *(uint4*)hb;
    }
}

__global__ void deg_count(const void* __restrict__ ei, int E) {
    __shared__ int s64;
    int is64 = detect64_local(ei, &s64);
    int i = blockIdx.x * blockDim.x + threadIdx.x;
    if (i >= E) return;
    int d = is64 ? (int)((const long long*)ei)[(size_t)E + i]
                 : ((const int*)ei)[(size_t)E + i];
    atomicAdd(&d_degi[d], 1);
}

__global__ void __launch_bounds__(SCAN_T)
scan_partial(int n) {
    __shared__ int ssum[SCAN_T];
    const int tid  = threadIdx.x;
    const int base = blockIdx.x * SCAN_C + tid * 4;
    int v[4];
#pragma unroll
    for (int i = 0; i < 4; ++i) {
        v[i] = (base + i < n) ? d_degi[base + i] : 0;
        if (base + i < n) d_dinv[base + i] = rsqrtf((float)v[i] + 1.0f);
    }
    int tsum = v[0] + v[1] + v[2] + v[3];
    ssum[tid] = tsum;
    __syncthreads();
    for (int off = 1; off < SCAN_T; off <<= 1) {
        int t = (tid >= off) ? ssum[tid - off] : 0;
        __syncthreads();
        ssum[tid] += t;
        __syncthreads();
    }
    int texcl = ssum[tid] - tsum;
    if (tid == SCAN_T - 1) d_blocksums[blockIdx.x] = ssum[tid];
    int run = texcl;
#pragma unroll
    for (int i = 0; i < 4; ++i) {
        if (base + i < n) d_off[base + i] = run;
        run += v[i];
    }
}

// scan_add: each block redundantly exclusive-scans the 25 chunk totals in
// a warp, then applies the chunk offset. Also re-zeroes d_degi.
__global__ void scan_add(int n, int E) {
    __shared__ int soff[SCAN_NBLK];
    if (threadIdx.x < 32) {
        int tid = threadIdx.x;
        int v = (tid < SCAN_NBLK) ? d_blocksums[tid] : 0;
        int orig = v;
#pragma unroll
        for (int o = 1; o < 32; o <<= 1) {
            int t = __shfl_up_sync(0xFFFFFFFFu, v, o);
            if (tid >= o) v += t;
        }
        if (tid < SCAN_NBLK) soff[tid] = v - orig;
    }
    __syncthreads();
    int i = blockIdx.x * blockDim.x + threadIdx.x;
    if (i < n) {
        int v = d_off[i] + soff[i / SCAN_C];
        d_off[i] = v;
        d_cursor[i] = v;
        d_degi[i] = 0;
    }
    if (i == 0) d_off[n] = E;
}

// scatter + W2 convert into the W2-only image (no race with gemm1).
__global__ void scatter_ws(const void* __restrict__ ei, int E, int sblk,
                           const float* __restrict__ W2) {
    if (blockIdx.x >= sblk) {
        int idx = (blockIdx.x - sblk) * 256 + threadIdx.x;
        if (idx < 16384) w_conv_elem(W2, d_W2h, idx);
        return;
    }
    __shared__ int s64;
    int is64 = detect64_local(ei, &s64);
    int i = blockIdx.x * blockDim.x + threadIdx.x;
    if (i >= E) return;
    int si, di;
    if (is64) {
        const long long* p = (const long long*)ei;
        si = (int)p[i];
        di = (int)p[(size_t)E + i];
    } else {
        const int* p = (const int*)ei;
        si = p[i];
        di = p[(size_t)E + i];
    }
    int pos = atomicAdd(&d_cursor[di], 1);
    d_csr[pos] = si;
}

// ---------------------------------------------------------------------------
// cp.async-pipelined persistent pure-fp16 HMMA GEMM.
//   gout[row] = fp16( dinv[row] * (A[row] @ W) ),  A/W single fp16 images.
// 32-row tiles, warp tile 16x32, 2-stage A ring, 3 blocks/SM.
__global__ void __launch_bounds__(256, 3)
gemm_tc(const unsigned short* __restrict__ Ah,
        const unsigned short* __restrict__ Wh,
        __half* __restrict__ gout, int n, int ntiles) {
    extern __shared__ char dsm[];
    char* sB = dsm;
    const uint32_t aBase = smem_u32(dsm + B_SH);   // 2 stages

    const int tid = threadIdx.x;
    const int wid = tid >> 5;
    const int lid = tid & 31;

    // Stage W image once (linear copy).
    {
        const float4* wsrc = (const float4*)Wh;
        float4* bdst = (float4*)sB;
        for (int i = tid; i < B_SH / 16; i += 256) bdst[i] = wsrc[i];
    }

    // Warp tiling: 16 rows x 32 cols.
    const int mrow0 = (wid >> 2) * 16;     // 0 or 16
    const int ncol0 = (wid & 3) * 32;      // 0,32,64,96
    const int sel   = lid >> 3;
    const int rowIn = lid & 7;
    const uint32_t aoff =
        (uint32_t)(((mrow0 + rowIn + (sel & 1) * 8) * BSTRIDE + (sel >> 1) * 8) * 2);
    const uint32_t boff =
        (uint32_t)(((ncol0 + (sel >> 1) * 8 + rowIn) * BSTRIDE + (sel & 1) * 8) * 2);
    const uint32_t bB = smem_u32(sB) + boff;

    // cp.async: 512 chunks = 32 rows x 16 chunks(16B). 2 per thread.
    auto issue = [&](int tt, int s) {
#pragma unroll
        for (int i = 0; i < 2; ++i) {
            int id = tid + i * 256;
            int r  = id >> 4;
            int c  = id & 15;
            int gr = tt * 32 + r;
            if (gr >= n) gr = n - 1;
            const unsigned short* src = Ah + (size_t)gr * FD + c * 8;
            uint32_t dst = aBase + s * A_STG + r * (BSTRIDE * 2) + c * 16;
            cp16(dst, src);
        }
        asm volatile("cp.async.commit_group;" ::: "memory");
    };

    int t = blockIdx.x;
    if (t < ntiles) issue(t, 0);
    int p = 0;

    for (; t < ntiles; t += gridDim.x) {
        const int tn = t + gridDim.x;
        if (tn < ntiles) {
            issue(tn, p ^ 1);
            asm volatile("cp.async.wait_group 1;" ::: "memory");
        } else {
            asm volatile("cp.async.wait_group 0;" ::: "memory");
        }
        __syncthreads();

        const uint32_t aB = aBase + p * A_STG + aoff;

        float acc[4][4];
#pragma unroll
        for (int j = 0; j < 4; ++j)
#pragma unroll
            for (int q = 0; q < 4; ++q) acc[j][q] = 0.f;

#pragma unroll
        for (int ks = 0; ks < 8; ++ks) {
            const uint32_t kb = ks * 32;
            uint32_t a[4], b2[4][2];
            ldm_x4(a, aB + kb);
#pragma unroll
            for (int j2 = 0; j2 < 2; ++j2) {
                uint32_t q[4];
                ldm_x4(q, bB + j2 * (16 * BSTRIDE * 2) + kb);
                b2[2 * j2][0] = q[0]; b2[2 * j2][1] = q[1];
                b2[2 * j2 + 1][0] = q[2]; b2[2 * j2 + 1][1] = q[3];
            }
#pragma unroll
            for (int j = 0; j < 4; ++j) mma_f16(acc[j], a, b2[j]);
        }

        // Epilogue: scale by dinv[row], convert fp16, store.
        {
            const int r1 = t * 32 + mrow0 + (lid >> 2);
            const int r2 = r1 + 8;
            const int cbase = ncol0 + 2 * (lid & 3);
            const float dv1 = (r1 < n) ? d_dinv[r1] : 0.f;
            const float dv2 = (r2 < n) ? d_dinv[r2] : 0.f;
#pragma unroll
            for (int j = 0; j < 4; ++j) {
                int c = cbase + 8 * j;
                if (r1 < n)
                    *(__half2*)(gout + (size_t)r1 * FD + c) =
                        __floats2half2_rn(acc[j][0] * dv1, acc[j][1] * dv1);
                if (r2 < n)
                    *(__half2*)(gout + (size_t)r2 * FD + c) =
                        __floats2half2_rn(acc[j][2] * dv2, acc[j][3] * dv2);
            }
        }
        __syncthreads();
        p ^= 1;
    }
}

// ---------------------------------------------------------------------------
// Fused aggregate: one warp per dst node, fp16 gather (g pre-scaled by dinv).
//   out[d] = dinv[d]*(Σ g[s] + g[d]) + b
// mode 1: relu, write h as single fp16 image. mode 0: write fp32 out.
__global__ void __launch_bounds__(256)
aggregate_csr(const __half* __restrict__ g, const float* __restrict__ bias,
              float* __restrict__ out, unsigned short* __restrict__ oh,
              int n, int mode) {
    const int w = blockIdx.x * 8 + (threadIdx.x >> 5);
    if (w >= n) return;
    const int lane = threadIdx.x & 31;

    const uint2* gw = (const uint2*)g + lane;

    float acc0, acc1, acc2, acc3;
    {
        uint2 raw = __ldg(gw + (size_t)w * 32);
        float2 f0 = __half22float2(*(__half2*)&raw.x);
        float2 f1 = __half22float2(*(__half2*)&raw.y);
        acc0 = f0.x; acc1 = f0.y; acc2 = f1.x; acc3 = f1.y;
    }

    int e = d_off[w];
    const int eend = d_off[w + 1];
    for (; e + 4 <= eend; e += 4) {
        int s0 = __ldg(&d_csr[e]);
        int s1 = __ldg(&d_csr[e + 1]);
        int s2 = __ldg(&d_csr[e + 2]);
        int s3 = __ldg(&d_csr[e + 3]);
        uint2 ra = __ldg(gw + (size_t)s0 * 32);
        uint2 rb = __ldg(gw + (size_t)s1 * 32);
        uint2 rc = __ldg(gw + (size_t)s2 * 32);
        uint2 rd = __ldg(gw + (size_t)s3 * 32);
        float2 a0 = __half22float2(*(__half2*)&ra.x), a1 = __half22float2(*(__half2*)&ra.y);
        float2 b0 = __half22float2(*(__half2*)&rb.x), b1 = __half22float2(*(__half2*)&rb.y);
        float2 c0 = __half22float2(*(__half2*)&rc.x), c1 = __half22float2(*(__half2*)&rc.y);
        float2 d0 = __half22float2(*(__half2*)&rd.x), d1 = __half22float2(*(__half2*)&rd.y);
        acc0 += (a0.x + b0.x) + (c0.x + d0.x);
        acc1 += (a0.y + b0.y) + (c0.y + d0.y);
        acc2 += (a1.x + b1.x) + (c1.x + d1.x);
        acc3 += (a1.y + b1.y) + (c1.y + d1.y);
    }
    for (; e < eend; ++e) {
        int s0 = __ldg(&d_csr[e]);
        uint2 ra = __ldg(gw + (size_t)s0 * 32);
        float2 a0 = __half22float2(*(__half2*)&ra.x), a1 = __half22float2(*(__half2*)&ra.y);
        acc0 += a0.x; acc1 += a0.y; acc2 += a1.x; acc3 += a1.y;
    }

    const float dv = d_dinv[w];
    float4 bs = __ldg((const float4*)bias + lane);
    float r0 = dv * acc0 + bs.x;
    float r1 = dv * acc1 + bs.y;
    float r2 = dv * acc2 + bs.z;
    float r3 = dv * acc3 + bs.w;

    if (mode) {
        r0 = fmaxf(r0, 0.f); r1 = fmaxf(r1, 0.f);
        r2 = fmaxf(r2, 0.f); r3 = fmaxf(r3, 0.f);
        alignas(8) unsigned short hb[4];
        hb[0] = hbits(__float2half_rn(r0));
        hb[1] = hbits(__float2half_rn(r1));
        hb[2] = hbits(__float2half_rn(r2));
        hb[3] = hbits(__float2half_rn(r3));
        *(uint2*)(oh + (size_t)w * FD + lane * 4) = *(uint2*)hb;
    } else {
        ((float4*)(out + (size_t)w * FD))[lane] = make_float4(r0, r1, r2, r3);
    }
}

// ---------------------------------------------------------------------------
extern "C" void kernel_launch(void* const* d_in, const int* in_sizes, int n_in,
                              void* d_out, int out_size) {
    const float* x  = (const float*)d_in[0];
    const void*  ei = d_in[1];
    const float* W1 = (const float*)d_in[2];
    const float* b1 = (const float*)d_in[3];
    const float* W2 = (const float*)d_in[4];
    const float* b2 = (const float*)d_in[5];
    float* out = (float*)d_out;

    int n = in_sizes[0] / FD;
    if (n > NMAX) n = NMAX;
    int E = in_sizes[1] / 2;
    if (E > EMAX) E = EMAX;

    float* bufA;
    unsigned short *xh, *hh, *w1h, *w2h;
    cudaGetSymbolAddress((void**)&bufA, d_bufA);
    cudaGetSymbolAddress((void**)&xh, d_xh);
    cudaGetSymbolAddress((void**)&hh, d_hh);
    cudaGetSymbolAddress((void**)&w1h, d_W1h);
    cudaGetSymbolAddress((void**)&w2h, d_W2h);
    __half* gbuf = (__half*)bufA;

    cudaFuncSetAttribute(gemm_tc,
                         cudaFuncAttributeMaxDynamicSharedMemorySize, GEMM_SMEM);

    static cudaStream_t s_side = []() {
        cudaStream_t s;
        cudaStreamCreateWithFlags(&s, cudaStreamNonBlocking);
        return s;
    }();
    static cudaEvent_t ev[3] = {};
    if (!ev[0])
        for (int i = 0; i < 3; ++i)
            cudaEventCreateWithFlags(&ev[i], cudaEventDisableTiming);
    cudaEvent_t e_fork = ev[0], e_dinv = ev[1], e_csr = ev[2];

    const int ntiles = (n + 31) / 32;
    const int ggrid = (ntiles < 3 * NSM) ? ntiles : 3 * NSM;
    const int sblk = (E + 255) / 256;

    // ---- main: fused W1 + x conversion (no dependencies) ----
    split_all<<<64 + 2 * NSM, 256>>>(x, W1, xh, n * 16);
    cudaEventRecord(e_fork, 0);

    // ---- side: degree -> dinv ----
    cudaStreamWaitEvent(s_side, e_fork, 0);
    deg_count<<<(E + 255) / 256, 256, 0, s_side>>>(ei, E);
    scan_partial<<<SCAN_NBLK, SCAN_T, 0, s_side>>>(n);   // produces dinv
    cudaEventRecord(e_dinv, s_side);

    // ---- main: gemm1 waits only for dinv ----
    cudaStreamWaitEvent(0, e_dinv, 0);
    gemm_tc<<<ggrid, 256, GEMM_SMEM>>>(xh, w1h, gbuf, n, ntiles);

    // ---- side: finish CSR (overlaps gemm1) ----
    scan_add<<<(n + 255) / 256, 256, 0, s_side>>>(n, E); // merged blocksum scan
    scatter_ws<<<sblk + 64, 256, 0, s_side>>>(ei, E, sblk, W2);
    cudaEventRecord(e_csr, s_side);

    // ---- main: agg1 (relu, h fp16) -> gemm2 -> agg2 ----
    cudaStreamWaitEvent(0, e_csr, 0);
    aggregate_csr<<<(n + 7) / 8, 256>>>(gbuf, b1, nullptr, hh, n, 1);
    gemm_tc<<<ggrid, 256, GEMM_SMEM>>>(hh, w2h, gbuf, n, ntiles);
    aggregate_csr<<<(n + 7) / 8, 256>>>(gbuf, b2, out, nullptr, n, 0);
}